// round 1
// baseline (speedup 1.0000x reference)
#include <cuda_runtime.h>
#include <cstdint>
#include <math.h>

#define NQ 65536
#define D  1024
#define NP 512
#define H  128

// Scratch (no allocations allowed): proto_h = prototypes @ W1b  [512,128], argmin idx [65536]
__device__ float g_proto_h[NP * H];
__device__ int   g_amin[NQ];

__device__ __forceinline__ uint32_t f2tf(float f) {
    uint32_t u;
    asm("cvt.rna.tf32.f32 %0, %1;" : "=r"(u) : "f"(f));
    return u;
}

__device__ __forceinline__ void mma_tf32(float d[4], const uint32_t a[4],
                                         uint32_t b0, uint32_t b1) {
    asm volatile(
        "mma.sync.aligned.m16n8k8.row.col.f32.tf32.tf32.f32 "
        "{%0,%1,%2,%3}, {%4,%5,%6,%7}, {%8,%9}, {%0,%1,%2,%3};\n"
        : "+f"(d[0]), "+f"(d[1]), "+f"(d[2]), "+f"(d[3])
        : "r"(a[0]), "r"(a[1]), "r"(a[2]), "r"(a[3]), "r"(b0), "r"(b1));
}

// ---------------------------------------------------------------------------
// Kernel A: proto_h[p][n] = sum_k prototypes[p][k] * W1[1024+k][n]   (fp32)
// grid 128 blocks x 256 threads, 4 prototypes per block.
// ---------------------------------------------------------------------------
__global__ void proto_h_kernel(const float* __restrict__ proto,
                               const float* __restrict__ W1) {
    __shared__ float ps[4 * D];
    int pb = blockIdx.x * 4;
    const float4* src = (const float4*)(proto + (size_t)pb * D);
    float4* dst = (float4*)ps;
    for (int i = threadIdx.x; i < 4 * D / 4; i += 256) dst[i] = src[i];
    __syncthreads();

    int n  = threadIdx.x & (H - 1);
    int pg = threadIdx.x >> 7;                 // 0/1 -> protos {2pg, 2pg+1}
    const float* ra = ps + (pg * 2) * D;
    const float* rb = ps + (pg * 2 + 1) * D;
    const float* w  = W1 + (size_t)D * H + n;  // W1b column n
    float a0 = 0.f, a1 = 0.f;
#pragma unroll 8
    for (int k = 0; k < D; k++) {
        float wv = __ldg(w + (size_t)k * H);
        a0 = fmaf(ra[k], wv, a0);
        a1 = fmaf(rb[k], wv, a1);
    }
    g_proto_h[(pb + pg * 2) * H + n]     = a0;
    g_proto_h[(pb + pg * 2 + 1) * H + n] = a1;
}

// ---------------------------------------------------------------------------
// Kernel B: per-query argmin over 512 distances. One warp per query.
// grid 8192 x 256 threads. Memory-bound: 128 MB.
// ---------------------------------------------------------------------------
__global__ void argmin_kernel(const float* __restrict__ dist) {
    int q    = blockIdx.x * 8 + (threadIdx.x >> 5);
    int lane = threadIdx.x & 31;
    const float4* row = (const float4*)(dist + (size_t)q * NP);
    float best = 3.402823466e+38f;
    int   bi   = 0;
#pragma unroll
    for (int i = 0; i < 4; i++) {
        int c4 = lane + i * 32;
        float4 v = __ldg(row + c4);
        int c = c4 * 4;
        if (v.x < best) { best = v.x; bi = c; }
        if (v.y < best) { best = v.y; bi = c + 1; }
        if (v.z < best) { best = v.z; bi = c + 2; }
        if (v.w < best) { best = v.w; bi = c + 3; }
    }
#pragma unroll
    for (int off = 16; off; off >>= 1) {
        float ov = __shfl_xor_sync(0xffffffffu, best, off);
        int   oi = __shfl_xor_sync(0xffffffffu, bi, off);
        if (ov < best || (ov == best && oi < bi)) { best = ov; bi = oi; }
    }
    if (lane == 0) g_amin[q] = bi;
}

// ---------------------------------------------------------------------------
// Kernel C: fused qh = qf @ W1a (tf32 mma.sync), + proto_h[idx] + b1, relu,
//           dot W2, + b2, sigmoid.
// Block tile M=128 x N=128(full), K-step 32. 256 threads = 8 warps (4Mx2N),
// warp tile 32x64, mma m16n8k8. XOR-swizzled SMEM: conflict-free ld/st.
// ---------------------------------------------------------------------------
__global__ __launch_bounds__(256, 2)
void fused_kernel(const float* __restrict__ qf, const float* __restrict__ W1,
                  const float* __restrict__ b1, const float* __restrict__ W2,
                  const float* __restrict__ b2, float* __restrict__ out) {
    __shared__ uint32_t Ash[128 * 32];   // [m][k^((m&7)*4)]
    __shared__ uint32_t Bsh[32 * 128];   // [k][n^((k&3)*8)]
    __shared__ float b1s[H], w2s[H];
    __shared__ float psum[128 * 2];

    int tid = threadIdx.x;
    if (tid < H) { b1s[tid] = b1[tid]; w2s[tid] = W2[tid]; }

    int mblock = blockIdx.x * 128;
    int warp = tid >> 5, lane = tid & 31;
    int wm = warp >> 1, wn = warp & 1;
    int g = lane >> 2, tig = lane & 3;

    float acc[2][8][4];
#pragma unroll
    for (int a = 0; a < 2; a++)
#pragma unroll
        for (int bq = 0; bq < 8; bq++)
#pragma unroll
            for (int c = 0; c < 4; c++) acc[a][bq][c] = 0.f;

    for (int kt = 0; kt < D; kt += 32) {
        __syncthreads();
        // A tile: qf[mblock..+128][kt..+32] -> tf32, swizzled
#pragma unroll
        for (int t = 0; t < 4; t++) {
            int idx = tid + t * 256;
            int m = idx >> 3, k4 = idx & 7;
            float4 v = *(const float4*)(qf + (size_t)(mblock + m) * D + kt + k4 * 4);
            int kp = (k4 * 4) ^ ((m & 7) * 4);
            uint32_t* p = &Ash[m * 32 + kp];
            p[0] = f2tf(v.x); p[1] = f2tf(v.y); p[2] = f2tf(v.z); p[3] = f2tf(v.w);
        }
        // B tile: W1a rows kt..kt+32, all 128 cols -> tf32, swizzled
#pragma unroll
        for (int t = 0; t < 4; t++) {
            int idx = tid + t * 256;
            int k = idx >> 5, n4 = idx & 31;
            float4 v = *(const float4*)(W1 + (size_t)(kt + k) * H + n4 * 4);
            int np = (n4 * 4) ^ ((k & 3) * 8);
            uint32_t* p = &Bsh[k * 128 + np];
            p[0] = f2tf(v.x); p[1] = f2tf(v.y); p[2] = f2tf(v.z); p[3] = f2tf(v.w);
        }
        __syncthreads();
#pragma unroll
        for (int kc = 0; kc < 4; kc++) {
            uint32_t af[2][4];
#pragma unroll
            for (int mt = 0; mt < 2; mt++) {
                int m0  = wm * 32 + mt * 16 + g;
                int ks0 = (kc * 8 + tig)     ^ (g * 4);
                int ks2 = (kc * 8 + tig + 4) ^ (g * 4);
                af[mt][0] = Ash[m0 * 32 + ks0];
                af[mt][1] = Ash[(m0 + 8) * 32 + ks0];
                af[mt][2] = Ash[m0 * 32 + ks2];
                af[mt][3] = Ash[(m0 + 8) * 32 + ks2];
            }
#pragma unroll
            for (int nt = 0; nt < 8; nt++) {
                int n = wn * 64 + nt * 8 + g;
                uint32_t bb0 = Bsh[(kc * 8 + tig) * 128     + (n ^ (tig * 8))];
                uint32_t bb1 = Bsh[(kc * 8 + tig + 4) * 128 + (n ^ (tig * 8))];
                mma_tf32(acc[0][nt], af[0], bb0, bb1);
                mma_tf32(acc[1][nt], af[1], bb0, bb1);
            }
        }
    }

    // Epilogue: h = relu(qh + proto_h[idx] + b1); partial logit = h . W2
    float b2v = __ldg(b2);
#pragma unroll
    for (int mt = 0; mt < 2; mt++) {
#pragma unroll
        for (int h = 0; h < 2; h++) {
            int rloc = wm * 32 + mt * 16 + h * 8 + g;
            int r = mblock + rloc;
            const float* ph = g_proto_h + (size_t)g_amin[r] * H;
            float p = 0.f;
#pragma unroll
            for (int nt = 0; nt < 8; nt++) {
#pragma unroll
                for (int j = 0; j < 2; j++) {
                    int n = wn * 64 + nt * 8 + tig * 2 + j;
                    float v = acc[mt][nt][h * 2 + j] + ph[n] + b1s[n];
                    p += fmaxf(v, 0.f) * w2s[n];
                }
            }
            p += __shfl_xor_sync(0xffffffffu, p, 1);
            p += __shfl_xor_sync(0xffffffffu, p, 2);
            if (tig == 0) psum[rloc * 2 + wn] = p;
        }
    }
    __syncthreads();
    if (tid < 128) {
        float logit = psum[tid * 2] + psum[tid * 2 + 1] + b2v;
        out[mblock + tid] = 1.f / (1.f + __expf(-logit));
    }
}

// ---------------------------------------------------------------------------
extern "C" void kernel_launch(void* const* d_in, const int* in_sizes, int n_in,
                              void* d_out, int out_size) {
    const float* qf    = (const float*)d_in[0];
    const float* proto = (const float*)d_in[1];
    const float* dist  = (const float*)d_in[2];
    const float* W1    = (const float*)d_in[3];
    const float* b1    = (const float*)d_in[4];
    const float* W2    = (const float*)d_in[5];
    const float* b2    = (const float*)d_in[6];
    float* out = (float*)d_out;

    proto_h_kernel<<<NP / 4, 256>>>(proto, W1);
    argmin_kernel<<<NQ / 8, 256>>>(dist);
    fused_kernel<<<NQ / 128, 256>>>(qf, W1, b1, W2, b2, out);
}

// round 2
// speedup vs baseline: 1.4476x; 1.4476x over previous
#include <cuda_runtime.h>
#include <cstdint>
#include <math.h>

#define NQ 65536
#define D  1024
#define NP 512
#define H  128

// Scratch: proto_h = prototypes @ W1b  [512,128]
__device__ float g_proto_h[NP * H];

__device__ __forceinline__ void mma_tf32(float d[4], const uint32_t a[4],
                                         uint32_t b0, uint32_t b1) {
    asm volatile(
        "mma.sync.aligned.m16n8k8.row.col.f32.tf32.tf32.f32 "
        "{%0,%1,%2,%3}, {%4,%5,%6,%7}, {%8,%9}, {%0,%1,%2,%3};\n"
        : "+f"(d[0]), "+f"(d[1]), "+f"(d[2]), "+f"(d[3])
        : "r"(a[0]), "r"(a[1]), "r"(a[2]), "r"(a[3]), "r"(b0), "r"(b1));
}

__device__ __forceinline__ void cpa16(uint32_t s, const void* g) {
    asm volatile("cp.async.cg.shared.global [%0], [%1], 16;\n" :: "r"(s), "l"(g));
}
__device__ __forceinline__ void cp_commit() {
    asm volatile("cp.async.commit_group;\n" ::: "memory");
}

// ---------------------------------------------------------------------------
// Kernel A: proto_h[p][n] = sum_k proto[p][k] * W1[1024+k][n]
// smem-tiled fp32: 128 blocks x 4 protos, k-chunks of 64, coalesced W loads.
// ---------------------------------------------------------------------------
__global__ __launch_bounds__(256)
void proto_h_kernel(const float* __restrict__ proto, const float* __restrict__ W1) {
    __shared__ float Wt[64 * 128];   // 32 KB
    __shared__ float Pt[4 * 64];     // 1 KB
    int tid = threadIdx.x;
    int pb = blockIdx.x * 4;
    int n = tid & 127, rg = tid >> 7;            // rg 0/1 -> rows {2rg, 2rg+1}
    const float* W1b = W1 + (size_t)D * H;
    float a0 = 0.f, a1 = 0.f;

    for (int k0 = 0; k0 < D; k0 += 64) {
        __syncthreads();
#pragma unroll
        for (int i = 0; i < 8; i++) {
            int idx = tid + i * 256;             // 0..2047 float4
            int r = idx >> 5, c4 = idx & 31;
            *(float4*)&Wt[r * 128 + c4 * 4] =
                *(const float4*)(W1b + (size_t)(k0 + r) * H + c4 * 4);
        }
        if (tid < 64) {
            int r = tid >> 4, c4 = tid & 15;
            *(float4*)&Pt[r * 64 + c4 * 4] =
                *(const float4*)(proto + (size_t)(pb + r) * D + k0 + c4 * 4);
        }
        __syncthreads();
        const float* p0 = Pt + (rg * 2) * 64;
        const float* p1 = Pt + (rg * 2 + 1) * 64;
#pragma unroll
        for (int kk = 0; kk < 64; kk += 4) {
            float4 x0 = *(const float4*)(p0 + kk);
            float4 x1 = *(const float4*)(p1 + kk);
            float w0 = Wt[(kk + 0) * 128 + n];
            float w1 = Wt[(kk + 1) * 128 + n];
            float w2 = Wt[(kk + 2) * 128 + n];
            float w3 = Wt[(kk + 3) * 128 + n];
            a0 = fmaf(x0.x, w0, a0); a0 = fmaf(x0.y, w1, a0);
            a0 = fmaf(x0.z, w2, a0); a0 = fmaf(x0.w, w3, a0);
            a1 = fmaf(x1.x, w0, a1); a1 = fmaf(x1.y, w1, a1);
            a1 = fmaf(x1.z, w2, a1); a1 = fmaf(x1.w, w3, a1);
        }
    }
    g_proto_h[(pb + rg * 2) * H + n]     = a0;
    g_proto_h[(pb + rg * 2 + 1) * H + n] = a1;
}

// ---------------------------------------------------------------------------
// Kernel B: fused qh = qf @ W1a (tf32 mma, cp.async double-buffered), with
// per-row argmin over distances folded into the mainloop (1 row/warp/iter,
// prefetched one iteration ahead), epilogue: +proto_h[idx]+b1, relu, .W2,
// +b2, sigmoid.
// ---------------------------------------------------------------------------
#define A_WORDS  4096                      // 128*32
#define B_WORDS  4096                      // 32*128
#define SMEM_FUSED (2*A_WORDS*4 + 2*B_WORDS*4 + 128*4 + 128*4 + 128*4 + 256*4)

__device__ __forceinline__ void load_tiles(const float* __restrict__ qf,
                                           const float* __restrict__ W1,
                                           int mblock, int kt,
                                           uint32_t aBase, uint32_t bBase, int tid) {
#pragma unroll
    for (int i = 0; i < 4; i++) {
        int idx = tid + i * 256;
        int m = idx >> 3, k4 = idx & 7;
        uint32_t off = (uint32_t)(m * 32 + ((k4 * 4) ^ ((m & 7) * 4))) * 4u;
        cpa16(aBase + off, qf + (size_t)(mblock + m) * D + kt + k4 * 4);
    }
#pragma unroll
    for (int i = 0; i < 4; i++) {
        int idx = tid + i * 256;
        int k = idx >> 5, n4 = idx & 31;
        uint32_t off = (uint32_t)(k * 128 + ((n4 * 4) ^ ((k & 3) * 8))) * 4u;
        cpa16(bBase + off, W1 + (size_t)(kt + k) * H + n4 * 4);
    }
}

__global__ __launch_bounds__(256, 2)
void fused_kernel(const float* __restrict__ qf, const float* __restrict__ W1,
                  const float* __restrict__ b1, const float* __restrict__ W2,
                  const float* __restrict__ b2, const float* __restrict__ dist,
                  float* __restrict__ out) {
    extern __shared__ char smem[];
    uint32_t* Ash = (uint32_t*)smem;                       // [2][4096]
    uint32_t* Bsh = (uint32_t*)(smem + 2 * A_WORDS * 4);   // [2][4096]
    float* b1s    = (float*)(smem + 2 * A_WORDS * 4 + 2 * B_WORDS * 4);
    float* w2s    = b1s + 128;
    int*   amin_s = (int*)(w2s + 128);
    float* psum   = (float*)(amin_s + 128);

    int tid = threadIdx.x;
    int mblock = blockIdx.x * 128;
    int warp = tid >> 5, lane = tid & 31;
    int wm = warp >> 1, wn = warp & 1;
    int g = lane >> 2, tig = lane & 3;

    uint32_t aBase = (uint32_t)__cvta_generic_to_shared(Ash);
    uint32_t bBase = (uint32_t)__cvta_generic_to_shared(Bsh);

    // prologue: stage tile 0
    load_tiles(qf, W1, mblock, 0, aBase, bBase, tid);
    cp_commit();

    if (tid < 128) { b1s[tid] = b1[tid]; w2s[tid] = W2[tid]; }

    // argmin: warp handles rows [warp*16, warp*16+16); prefetch row 0
    const float* dbase = dist + (size_t)(mblock + warp * 16) * NP;
    float4 av0, av1, av2, av3;
    {
        const float4* rp = (const float4*)dbase;
        av0 = rp[lane]; av1 = rp[lane + 32]; av2 = rp[lane + 64]; av3 = rp[lane + 96];
    }

    float acc[2][8][4];
#pragma unroll
    for (int a = 0; a < 2; a++)
#pragma unroll
        for (int bq = 0; bq < 8; bq++)
#pragma unroll
            for (int c = 0; c < 4; c++) acc[a][bq][c] = 0.f;

    for (int t = 0; t < 32; t++) {
        if (t < 31) {
            load_tiles(qf, W1, mblock, (t + 1) * 32, aBase + (((t + 1) & 1) * A_WORDS) * 4,
                       bBase + (((t + 1) & 1) * B_WORDS) * 4, tid);
            cp_commit();
        }
        if (t < 16) {
            // reduce prefetched row t
            float best = 3.402823466e+38f; int bi = 0;
            float4 vv;
#pragma unroll
            for (int i = 0; i < 4; i++) {
                vv = (i == 0) ? av0 : (i == 1) ? av1 : (i == 2) ? av2 : av3;
                int c = (lane + i * 32) * 4;
                if (vv.x < best) { best = vv.x; bi = c; }
                if (vv.y < best) { best = vv.y; bi = c + 1; }
                if (vv.z < best) { best = vv.z; bi = c + 2; }
                if (vv.w < best) { best = vv.w; bi = c + 3; }
            }
#pragma unroll
            for (int off = 16; off; off >>= 1) {
                float ov = __shfl_xor_sync(0xffffffffu, best, off);
                int   oi = __shfl_xor_sync(0xffffffffu, bi, off);
                if (ov < best || (ov == best && oi < bi)) { best = ov; bi = oi; }
            }
            if (lane == 0) amin_s[warp * 16 + t] = bi;
            if (t + 1 < 16) {  // prefetch row t+1
                const float4* rp = (const float4*)(dbase + (size_t)(t + 1) * NP);
                av0 = rp[lane]; av1 = rp[lane + 32]; av2 = rp[lane + 64]; av3 = rp[lane + 96];
            }
        }
        if (t < 31) { asm volatile("cp.async.wait_group 1;\n" ::: "memory"); }
        else        { asm volatile("cp.async.wait_group 0;\n" ::: "memory"); }
        __syncthreads();

        const uint32_t* As = Ash + (t & 1) * A_WORDS;
        const uint32_t* Bs = Bsh + (t & 1) * B_WORDS;
#pragma unroll
        for (int kc = 0; kc < 4; kc++) {
            uint32_t af[2][4];
#pragma unroll
            for (int mt = 0; mt < 2; mt++) {
                int m0  = wm * 32 + mt * 16 + g;
                int ks0 = (kc * 8 + tig)     ^ (g * 4);
                int ks2 = (kc * 8 + tig + 4) ^ (g * 4);
                af[mt][0] = As[m0 * 32 + ks0];
                af[mt][1] = As[(m0 + 8) * 32 + ks0];
                af[mt][2] = As[m0 * 32 + ks2];
                af[mt][3] = As[(m0 + 8) * 32 + ks2];
            }
#pragma unroll
            for (int nt = 0; nt < 8; nt++) {
                int n = wn * 64 + nt * 8 + g;
                uint32_t bb0 = Bs[(kc * 8 + tig) * 128     + (n ^ (tig * 8))];
                uint32_t bb1 = Bs[(kc * 8 + tig + 4) * 128 + (n ^ (tig * 8))];
                mma_tf32(acc[0][nt], af[0], bb0, bb1);
                mma_tf32(acc[1][nt], af[1], bb0, bb1);
            }
        }
        __syncthreads();
    }

    // Epilogue: h = relu(qh + proto_h[idx] + b1); partial logit = h . W2
    float b2v = __ldg(b2);
#pragma unroll
    for (int mt = 0; mt < 2; mt++) {
#pragma unroll
        for (int hh = 0; hh < 2; hh++) {
            int rloc = wm * 32 + mt * 16 + hh * 8 + g;
            const float* ph = g_proto_h + (size_t)amin_s[rloc] * H;
            float p = 0.f;
#pragma unroll
            for (int nt = 0; nt < 8; nt++) {
#pragma unroll
                for (int j = 0; j < 2; j++) {
                    int n = wn * 64 + nt * 8 + tig * 2 + j;
                    float v = acc[mt][nt][hh * 2 + j] + ph[n] + b1s[n];
                    p += fmaxf(v, 0.f) * w2s[n];
                }
            }
            p += __shfl_xor_sync(0xffffffffu, p, 1);
            p += __shfl_xor_sync(0xffffffffu, p, 2);
            if (tig == 0) psum[rloc * 2 + wn] = p;
        }
    }
    __syncthreads();
    if (tid < 128) {
        float logit = psum[tid * 2] + psum[tid * 2 + 1] + b2v;
        out[mblock + tid] = 1.f / (1.f + __expf(-logit));
    }
}

// ---------------------------------------------------------------------------
extern "C" void kernel_launch(void* const* d_in, const int* in_sizes, int n_in,
                              void* d_out, int out_size) {
    const float* qf    = (const float*)d_in[0];
    const float* proto = (const float*)d_in[1];
    const float* dist  = (const float*)d_in[2];
    const float* W1    = (const float*)d_in[3];
    const float* b1    = (const float*)d_in[4];
    const float* W2    = (const float*)d_in[5];
    const float* b2    = (const float*)d_in[6];
    float* out = (float*)d_out;

    static int attr_set = 0;
    if (!attr_set) {
        cudaFuncSetAttribute(fused_kernel,
                             cudaFuncAttributeMaxDynamicSharedMemorySize, SMEM_FUSED);
        attr_set = 1;
    }

    proto_h_kernel<<<NP / 4, 256>>>(proto, W1);
    fused_kernel<<<NQ / 128, 256, SMEM_FUSED>>>(qf, W1, b1, W2, b2, dist, out);
}

// round 4
// speedup vs baseline: 1.6111x; 1.1129x over previous
#include <cuda_runtime.h>
#include <cstdint>
#include <math.h>

#define NQ 65536
#define D  1024
#define NP 512
#define H  128
#define KSPLIT 4

// Scratch (device globals; no allocations allowed)
__device__ float g_ph_part[KSPLIT * NP * H];   // split-k partials of prototypes @ W1b
__device__ float g_proto_h[NP * H];            // reduced [512,128]

__device__ __forceinline__ void mma_tf32(float d[4], const uint32_t a[4],
                                         uint32_t b0, uint32_t b1) {
    asm volatile(
        "mma.sync.aligned.m16n8k8.row.col.f32.tf32.tf32.f32 "
        "{%0,%1,%2,%3}, {%4,%5,%6,%7}, {%8,%9}, {%0,%1,%2,%3};\n"
        : "+f"(d[0]), "+f"(d[1]), "+f"(d[2]), "+f"(d[3])
        : "r"(a[0]), "r"(a[1]), "r"(a[2]), "r"(a[3]), "r"(b0), "r"(b1));
}
__device__ __forceinline__ void cpa16(uint32_t s, const void* g) {
    asm volatile("cp.async.cg.shared.global [%0], [%1], 16;\n" :: "r"(s), "l"(g));
}
__device__ __forceinline__ void cp_commit() {
    asm volatile("cp.async.commit_group;\n" ::: "memory");
}

// ---------------------------------------------------------------------------
// Kernel 1: split-k partials  g_ph_part[ks][p][n] = sum_{k in split} proto*W1b
// grid (128, 4) x 256
// ---------------------------------------------------------------------------
__global__ __launch_bounds__(256)
void proto_part_kernel(const float* __restrict__ proto, const float* __restrict__ W1) {
    __shared__ float Wt[64 * 128];
    __shared__ float Pt[4 * 64];
    int tid = threadIdx.x;
    int pb = blockIdx.x * 4;
    int kbase = blockIdx.y * (D / KSPLIT);
    int n = tid & 127, rg = tid >> 7;
    const float* W1b = W1 + (size_t)D * H;
    float a0 = 0.f, a1 = 0.f;

    for (int kc = 0; kc < D / KSPLIT; kc += 64) {
        int k0 = kbase + kc;
        __syncthreads();
#pragma unroll
        for (int i = 0; i < 8; i++) {
            int idx = tid + i * 256;
            int r = idx >> 5, c4 = idx & 31;
            *(float4*)&Wt[r * 128 + c4 * 4] =
                *(const float4*)(W1b + (size_t)(k0 + r) * H + c4 * 4);
        }
        if (tid < 64) {
            int r = tid >> 4, c4 = tid & 15;
            *(float4*)&Pt[r * 64 + c4 * 4] =
                *(const float4*)(proto + (size_t)(pb + r) * D + k0 + c4 * 4);
        }
        __syncthreads();
        const float* p0 = Pt + (rg * 2) * 64;
        const float* p1 = Pt + (rg * 2 + 1) * 64;
#pragma unroll
        for (int kk = 0; kk < 64; kk += 4) {
            float4 x0 = *(const float4*)(p0 + kk);
            float4 x1 = *(const float4*)(p1 + kk);
            float w0 = Wt[(kk + 0) * 128 + n];
            float w1 = Wt[(kk + 1) * 128 + n];
            float w2 = Wt[(kk + 2) * 128 + n];
            float w3 = Wt[(kk + 3) * 128 + n];
            a0 = fmaf(x0.x, w0, a0); a0 = fmaf(x0.y, w1, a0);
            a0 = fmaf(x0.z, w2, a0); a0 = fmaf(x0.w, w3, a0);
            a1 = fmaf(x1.x, w0, a1); a1 = fmaf(x1.y, w1, a1);
            a1 = fmaf(x1.z, w2, a1); a1 = fmaf(x1.w, w3, a1);
        }
    }
    g_ph_part[((size_t)blockIdx.y * NP + pb + rg * 2) * H + n]     = a0;
    g_ph_part[((size_t)blockIdx.y * NP + pb + rg * 2 + 1) * H + n] = a1;
}

// Kernel 2: reduce partials. grid 64 x 256, one float4 each.
__global__ void reduce_ph_kernel() {
    int i = blockIdx.x * 256 + threadIdx.x;   // float4 index, 16384 total
    float4 s = ((const float4*)g_ph_part)[i];
#pragma unroll
    for (int k = 1; k < KSPLIT; k++) {
        float4 v = ((const float4*)g_ph_part)[k * (NP * H / 4) + i];
        s.x += v.x; s.y += v.y; s.z += v.z; s.w += v.w;
    }
    ((float4*)g_proto_h)[i] = s;
}

// ---------------------------------------------------------------------------
// Kernel 3: fused qh = qf @ W1a (tf32 mma.sync, 3-stage cp.async ring, single
// __syncthreads per k-tile), argmin folded in, MLP epilogue.
// ---------------------------------------------------------------------------
#define A_WORDS  4096                      // 128*32
#define B_WORDS  4096                      // 32*128
#define STAGE_BYTES ((A_WORDS + B_WORDS) * 4)      // 32 KB
#define OFF_AUX   (3 * STAGE_BYTES)                // 96 KB
#define SMEM_FUSED (OFF_AUX + 128*4 + 128*4 + 128*4 + 256*4)

__device__ __forceinline__ void load_tiles(const float* __restrict__ qf,
                                           const float* __restrict__ W1,
                                           int mblock, int kt,
                                           uint32_t stageBase, int tid) {
    uint32_t aBase = stageBase;
    uint32_t bBase = stageBase + A_WORDS * 4;
#pragma unroll
    for (int i = 0; i < 4; i++) {
        int idx = tid + i * 256;
        int m = idx >> 3, k4 = idx & 7;
        uint32_t off = (uint32_t)(m * 32 + ((k4 * 4) ^ ((m & 7) * 4))) * 4u;
        cpa16(aBase + off, qf + (size_t)(mblock + m) * D + kt + k4 * 4);
    }
#pragma unroll
    for (int i = 0; i < 4; i++) {
        int idx = tid + i * 256;
        int k = idx >> 5, n4 = idx & 31;
        uint32_t off = (uint32_t)(k * 128 + ((n4 * 4) ^ ((k & 3) * 8))) * 4u;
        cpa16(bBase + off, W1 + (size_t)(kt + k) * H + n4 * 4);
    }
}

__global__ __launch_bounds__(256, 2)
void fused_kernel(const float* __restrict__ qf, const float* __restrict__ W1,
                  const float* __restrict__ b1, const float* __restrict__ W2,
                  const float* __restrict__ b2, const float* __restrict__ dist,
                  float* __restrict__ out) {
    extern __shared__ char smem[];
    uint32_t sb = (uint32_t)__cvta_generic_to_shared(smem);
    float* b1s    = (float*)(smem + OFF_AUX);
    float* w2s    = b1s + 128;
    int*   amin_s = (int*)(w2s + 128);
    float* psum   = (float*)(amin_s + 128);

    int tid = threadIdx.x;
    int mblock = blockIdx.x * 128;
    int warp = tid >> 5, lane = tid & 31;
    int wm = warp >> 1, wn = warp & 1;
    int g = lane >> 2, tig = lane & 3;

    // prologue: stage 0 and 1
    load_tiles(qf, W1, mblock, 0, sb, tid);
    cp_commit();
    load_tiles(qf, W1, mblock, 32, sb + STAGE_BYTES, tid);
    cp_commit();

    if (tid < 128) { b1s[tid] = b1[tid]; w2s[tid] = W2[tid]; }

    // argmin: warp handles rows [warp*16, warp*16+16); prefetch row 0
    const float* dbase = dist + (size_t)(mblock + warp * 16) * NP;
    float4 av0, av1, av2, av3;
    {
        const float4* rp = (const float4*)dbase;
        av0 = rp[lane]; av1 = rp[lane + 32]; av2 = rp[lane + 64]; av3 = rp[lane + 96];
    }

    float acc[2][8][4];
#pragma unroll
    for (int a = 0; a < 2; a++)
#pragma unroll
        for (int bq = 0; bq < 8; bq++)
#pragma unroll
            for (int c = 0; c < 4; c++) acc[a][bq][c] = 0.f;

    for (int t = 0; t < 32; t++) {
        // stage t is complete when <=1 groups pending (t, t+1 are the only
        // possibly-pending commits at this point)
        asm volatile("cp.async.wait_group 1;" ::: "memory");
        __syncthreads();
        // buffer (t+2)%3 was fully consumed by end of iter t-1 -> safe to refill
        if (t + 2 < 32) {
            load_tiles(qf, W1, mblock, (t + 2) * 32,
                       sb + ((t + 2) % 3) * STAGE_BYTES, tid);
            cp_commit();
        }
        if (t < 16) {
            float best = 3.402823466e+38f; int bi = 0;
            float4 vv;
#pragma unroll
            for (int i = 0; i < 4; i++) {
                vv = (i == 0) ? av0 : (i == 1) ? av1 : (i == 2) ? av2 : av3;
                int c = (lane + i * 32) * 4;
                if (vv.x < best) { best = vv.x; bi = c; }
                if (vv.y < best) { best = vv.y; bi = c + 1; }
                if (vv.z < best) { best = vv.z; bi = c + 2; }
                if (vv.w < best) { best = vv.w; bi = c + 3; }
            }
#pragma unroll
            for (int off = 16; off; off >>= 1) {
                float ov = __shfl_xor_sync(0xffffffffu, best, off);
                int   oi = __shfl_xor_sync(0xffffffffu, bi, off);
                if (ov < best || (ov == best && oi < bi)) { best = ov; bi = oi; }
            }
            if (lane == 0) amin_s[warp * 16 + t] = bi;
            if (t + 1 < 16) {
                const float4* rp = (const float4*)(dbase + (size_t)(t + 1) * NP);
                av0 = rp[lane]; av1 = rp[lane + 32]; av2 = rp[lane + 64]; av3 = rp[lane + 96];
            }
        }

        const uint32_t* As = (const uint32_t*)(smem + (t % 3) * STAGE_BYTES);
        const uint32_t* Bs = As + A_WORDS;
#pragma unroll
        for (int kc = 0; kc < 4; kc++) {
            uint32_t af[2][4];
#pragma unroll
            for (int mt = 0; mt < 2; mt++) {
                int m0  = wm * 32 + mt * 16 + g;
                int ks0 = (kc * 8 + tig)     ^ (g * 4);
                int ks2 = (kc * 8 + tig + 4) ^ (g * 4);
                af[mt][0] = As[m0 * 32 + ks0];
                af[mt][1] = As[(m0 + 8) * 32 + ks0];
                af[mt][2] = As[m0 * 32 + ks2];
                af[mt][3] = As[(m0 + 8) * 32 + ks2];
            }
#pragma unroll
            for (int nt = 0; nt < 8; nt++) {
                int n = wn * 64 + nt * 8 + g;
                uint32_t bb0 = Bs[(kc * 8 + tig) * 128     + (n ^ (tig * 8))];
                uint32_t bb1 = Bs[(kc * 8 + tig + 4) * 128 + (n ^ (tig * 8))];
                mma_tf32(acc[0][nt], af[0], bb0, bb1);
                mma_tf32(acc[1][nt], af[1], bb0, bb1);
            }
        }
    }

    // Epilogue: h = relu(qh + proto_h[idx] + b1); partial logit = h . W2
    float b2v = __ldg(b2);
#pragma unroll
    for (int mt = 0; mt < 2; mt++) {
#pragma unroll
        for (int hh = 0; hh < 2; hh++) {
            int rloc = wm * 32 + mt * 16 + hh * 8 + g;
            const float* ph = g_proto_h + (size_t)amin_s[rloc] * H;
            float p = 0.f;
#pragma unroll
            for (int nt = 0; nt < 8; nt++) {
#pragma unroll
                for (int j = 0; j < 2; j++) {
                    int n = wn * 64 + nt * 8 + tig * 2 + j;
                    float v = acc[mt][nt][hh * 2 + j] + ph[n] + b1s[n];
                    p += fmaxf(v, 0.f) * w2s[n];
                }
            }
            p += __shfl_xor_sync(0xffffffffu, p, 1);
            p += __shfl_xor_sync(0xffffffffu, p, 2);
            if (tig == 0) psum[rloc * 2 + wn] = p;
        }
    }
    __syncthreads();
    if (tid < 128) {
        float logit = psum[tid * 2] + psum[tid * 2 + 1] + b2v;
        out[mblock + tid] = 1.f / (1.f + __expf(-logit));
    }
}

// ---------------------------------------------------------------------------
extern "C" void kernel_launch(void* const* d_in, const int* in_sizes, int n_in,
                              void* d_out, int out_size) {
    const float* qf    = (const float*)d_in[0];
    const float* proto = (const float*)d_in[1];
    const float* dist  = (const float*)d_in[2];
    const float* W1    = (const float*)d_in[3];
    const float* b1    = (const float*)d_in[4];
    const float* W2    = (const float*)d_in[5];
    const float* b2    = (const float*)d_in[6];
    float* out = (float*)d_out;

    static int attr_set = 0;
    if (!attr_set) {
        cudaFuncSetAttribute(fused_kernel,
                             cudaFuncAttributeMaxDynamicSharedMemorySize, SMEM_FUSED);
        attr_set = 1;
    }

    proto_part_kernel<<<dim3(NP / 4, KSPLIT), 256>>>(proto, W1);
    reduce_ph_kernel<<<NP * H / 4 / 256, 256>>>();
    fused_kernel<<<NQ / 128, 256, SMEM_FUSED>>>(qf, W1, b1, W2, b2, dist, out);
}

// round 5
// speedup vs baseline: 2.1633x; 1.3427x over previous
#include <cuda_runtime.h>
#include <cuda_bf16.h>
#include <cstdint>
#include <math.h>

#define NQ 65536
#define D  1024
#define NP 512
#define H  128
#define KSPLIT 4

// Scratch (device globals; no allocations allowed)
__device__ float    g_ph_part[KSPLIT * NP * H];  // split-k partials of proto @ W1b
__device__ float    g_proto_h[NP * H];           // reduced [512,128]
__device__ uint32_t g_W1T[H * D];                // W1^T as bf16x2: [n][k/2], k pairs

__device__ __forceinline__ uint32_t packbf(float lo, float hi) {
    uint32_t r;
    asm("cvt.rn.bf16x2.f32 %0, %1, %2;" : "=r"(r) : "f"(hi), "f"(lo));
    return r;
}
__device__ __forceinline__ void mma_bf16(float d[4], const uint32_t a[4],
                                         uint32_t b0, uint32_t b1) {
    asm volatile(
        "mma.sync.aligned.m16n8k16.row.col.f32.bf16.bf16.f32 "
        "{%0,%1,%2,%3}, {%4,%5,%6,%7}, {%8,%9}, {%0,%1,%2,%3};\n"
        : "+f"(d[0]), "+f"(d[1]), "+f"(d[2]), "+f"(d[3])
        : "r"(a[0]), "r"(a[1]), "r"(a[2]), "r"(a[3]), "r"(b0), "r"(b1));
}
__device__ __forceinline__ void cpa16(uint32_t s, const void* g) {
    asm volatile("cp.async.cg.shared.global [%0], [%1], 16;\n" :: "r"(s), "l"(g));
}
__device__ __forceinline__ void cp_commit() {
    asm volatile("cp.async.commit_group;\n" ::: "memory");
}

// ---------------------------------------------------------------------------
// Kernel 1: convert+transpose full W1 [2048][128] f32 -> g_W1T [128][2048] bf16
// grid (64, 4) x 256
// ---------------------------------------------------------------------------
__global__ __launch_bounds__(256)
void convert_w1t_kernel(const float* __restrict__ W1) {
    __shared__ float t[32][33];
    int kb = blockIdx.x * 32, nb = blockIdx.y * 32;
    int r = threadIdx.x >> 5, c = threadIdx.x & 31;
#pragma unroll
    for (int i = 0; i < 4; i++)
        t[r + i * 8][c] = W1[(size_t)(kb + r + i * 8) * H + nb + c];
    __syncthreads();
    int rr = threadIdx.x >> 4, c2 = threadIdx.x & 15;
#pragma unroll
    for (int i = 0; i < 2; i++) {
        int n = rr + i * 16;
        g_W1T[(size_t)(nb + n) * (D / 1) /* 2048 bf16 = 1024 u32 */ * 0 +
              (size_t)(nb + n) * 1024 + kb / 2 + c2] =
            packbf(t[c2 * 2][n], t[c2 * 2 + 1][n]);
    }
}

// ---------------------------------------------------------------------------
// Shared GEMM machinery: A fp32 in smem (swizzled 16B chunks), B bf16 [n][k].
// Stage: A 128x32 f32 (16 KB) + B 128 rows x 32 k bf16 (8 KB) = 24 KB. 3 stages.
// ---------------------------------------------------------------------------
#define A_FLOATS     4096                     // 128*32
#define B_U32        2048                     // 128*16
#define STAGE_BYTES  (A_FLOATS * 4 + B_U32 * 4)   // 24576
#define OFF_AUX      (3 * STAGE_BYTES)            // 73728
#define SMEM_FUSED   (OFF_AUX + 128*4 + 128*4 + 128*4 + 256*4)
#define SMEM_PROTO   OFF_AUX

// wcol2048 = u32 column base into g_W1T (k offset / 2)
__device__ __forceinline__ void load_stage(const float* __restrict__ Aglob,
                                           int arow0, int kt, int wk0,
                                           uint32_t stageBase, int tid) {
    uint32_t aB = stageBase;
    uint32_t bB = stageBase + A_FLOATS * 4;
#pragma unroll
    for (int i = 0; i < 4; i++) {               // A: 1024 16B chunks
        int idx = tid + i * 256;
        int r = idx >> 3, c = idx & 7;
        cpa16(aB + (uint32_t)(r * 32 + ((c ^ (r & 7)) * 4)) * 4u,
              Aglob + (size_t)(arow0 + r) * D + kt + c * 4);
    }
#pragma unroll
    for (int i = 0; i < 2; i++) {               // B: 512 16B chunks
        int idx = tid + i * 256;
        int n = idx >> 2, c = idx & 3;
        cpa16(bB + (uint32_t)(n * 16 + ((c ^ ((n >> 1) & 3)) * 4)) * 4u,
              g_W1T + (size_t)n * 1024 + wk0 + (kt >> 1) + c * 4);
    }
}

// One k32 tile of MMAs. As: float*, Bs32: u32*, acc[2][8][4].
__device__ __forceinline__ void tile_mma(const float* As, const uint32_t* Bs32,
                                         float acc[2][8][4],
                                         int wm, int wn, int g, int tig) {
#pragma unroll
    for (int kc = 0; kc < 2; kc++) {
        uint32_t af[2][4];
#pragma unroll
        for (int mt = 0; mt < 2; mt++) {
            int r1 = wm * 32 + mt * 16 + g;
            int r2 = r1 + 8;
            int cl = kc * 4 + (tig >> 1);
            int w  = (tig & 1) * 2;
            int col_lo = ((cl ^ g) << 2) + w;
            int col_hi = (((cl + 2) ^ g) << 2) + w;
            float2 flo1 = *(const float2*)(As + r1 * 32 + col_lo);
            float2 flo2 = *(const float2*)(As + r2 * 32 + col_lo);
            float2 fhi1 = *(const float2*)(As + r1 * 32 + col_hi);
            float2 fhi2 = *(const float2*)(As + r2 * 32 + col_hi);
            af[mt][0] = packbf(flo1.x, flo1.y);
            af[mt][1] = packbf(flo2.x, flo2.y);
            af[mt][2] = packbf(fhi1.x, fhi1.y);
            af[mt][3] = packbf(fhi2.x, fhi2.y);
        }
#pragma unroll
        for (int nt = 0; nt < 8; nt++) {
            int n = wn * 64 + nt * 8 + g;
            const uint32_t* Brow = Bs32 + n * 16;
            int sw = (n >> 1) & 3;
            uint32_t b0 = Brow[(((kc * 2)     ^ sw) << 2) + tig];
            uint32_t b1 = Brow[(((kc * 2 + 1) ^ sw) << 2) + tig];
            mma_bf16(acc[0][nt], af[0], b0, b1);
            mma_bf16(acc[1][nt], af[1], b0, b1);
        }
    }
}

// ---------------------------------------------------------------------------
// Kernel 2: proto partials via bf16 mma. grid (4, KSPLIT) x 256.
// A = prototypes[mb..mb+128], B = W1b cols (u32 offset 512 + ks*128), K=256.
// ---------------------------------------------------------------------------
__global__ __launch_bounds__(256, 2)
void proto_mma_kernel(const float* __restrict__ proto) {
    extern __shared__ char smem[];
    uint32_t sb = (uint32_t)__cvta_generic_to_shared(smem);
    int tid = threadIdx.x;
    int mb = blockIdx.x * 128;
    int ks = blockIdx.y;
    int kt0 = ks * 256;
    int wk0 = 512;                    // W1b starts at k=1024 -> u32 col 512
    int warp = tid >> 5, lane = tid & 31;
    int wm = warp >> 1, wn = warp & 1;
    int g = lane >> 2, tig = lane & 3;

    load_stage(proto, mb, kt0, wk0, sb, tid);               cp_commit();
    load_stage(proto, mb, kt0 + 32, wk0, sb + STAGE_BYTES, tid); cp_commit();

    float acc[2][8][4];
#pragma unroll
    for (int a = 0; a < 2; a++)
#pragma unroll
        for (int b = 0; b < 8; b++)
#pragma unroll
            for (int c = 0; c < 4; c++) acc[a][b][c] = 0.f;

    for (int t = 0; t < 8; t++) {
        if (t + 1 < 8) asm volatile("cp.async.wait_group 1;" ::: "memory");
        else           asm volatile("cp.async.wait_group 0;" ::: "memory");
        __syncthreads();
        if (t + 2 < 8) {
            load_stage(proto, mb, kt0 + (t + 2) * 32, wk0,
                       sb + ((t + 2) % 3) * STAGE_BYTES, tid);
            cp_commit();
        }
        const float* As = (const float*)(smem + (t % 3) * STAGE_BYTES);
        const uint32_t* Bs32 = (const uint32_t*)(As + A_FLOATS);
        tile_mma(As, Bs32, acc, wm, wn, g, tig);
    }

    float* dst = g_ph_part + (size_t)ks * NP * H;
#pragma unroll
    for (int mt = 0; mt < 2; mt++)
#pragma unroll
        for (int hh = 0; hh < 2; hh++)
#pragma unroll
            for (int nt = 0; nt < 8; nt++) {
                int row = mb + wm * 32 + mt * 16 + hh * 8 + g;
                int col = wn * 64 + nt * 8 + tig * 2;
                float2 v = make_float2(acc[mt][nt][hh * 2], acc[mt][nt][hh * 2 + 1]);
                *(float2*)(dst + (size_t)row * H + col) = v;
            }
}

// Kernel 3: reduce partials. grid 64 x 256.
__global__ void reduce_ph_kernel() {
    int i = blockIdx.x * 256 + threadIdx.x;
    float4 s = ((const float4*)g_ph_part)[i];
#pragma unroll
    for (int k = 1; k < KSPLIT; k++) {
        float4 v = ((const float4*)g_ph_part)[k * (NP * H / 4) + i];
        s.x += v.x; s.y += v.y; s.z += v.z; s.w += v.w;
    }
    ((float4*)g_proto_h)[i] = s;
}

// ---------------------------------------------------------------------------
// Kernel 4: fused qf @ W1a (bf16 mma), argmin folded in, MLP epilogue.
// ---------------------------------------------------------------------------
__global__ __launch_bounds__(256, 2)
void fused_kernel(const float* __restrict__ qf, const float* __restrict__ b1,
                  const float* __restrict__ W2, const float* __restrict__ b2,
                  const float* __restrict__ dist, float* __restrict__ out) {
    extern __shared__ char smem[];
    uint32_t sb = (uint32_t)__cvta_generic_to_shared(smem);
    float* b1s    = (float*)(smem + OFF_AUX);
    float* w2s    = b1s + 128;
    int*   amin_s = (int*)(w2s + 128);
    float* psum   = (float*)(amin_s + 128);

    int tid = threadIdx.x;
    int mblock = blockIdx.x * 128;
    int warp = tid >> 5, lane = tid & 31;
    int wm = warp >> 1, wn = warp & 1;
    int g = lane >> 2, tig = lane & 3;

    load_stage(qf, mblock, 0, 0, sb, tid);                cp_commit();
    load_stage(qf, mblock, 32, 0, sb + STAGE_BYTES, tid); cp_commit();

    if (tid < 128) { b1s[tid] = b1[tid]; w2s[tid] = W2[tid]; }

    // argmin: warp handles rows [warp*16, warp*16+16); prefetch row 0
    const float* dbase = dist + (size_t)(mblock + warp * 16) * NP;
    float4 av0, av1, av2, av3;
    {
        const float4* rp = (const float4*)dbase;
        av0 = rp[lane]; av1 = rp[lane + 32]; av2 = rp[lane + 64]; av3 = rp[lane + 96];
    }

    float acc[2][8][4];
#pragma unroll
    for (int a = 0; a < 2; a++)
#pragma unroll
        for (int b = 0; b < 8; b++)
#pragma unroll
            for (int c = 0; c < 4; c++) acc[a][b][c] = 0.f;

    for (int t = 0; t < 32; t++) {
        if (t + 1 < 32) asm volatile("cp.async.wait_group 1;" ::: "memory");
        else            asm volatile("cp.async.wait_group 0;" ::: "memory");
        __syncthreads();
        if (t + 2 < 32) {
            load_stage(qf, mblock, (t + 2) * 32, 0,
                       sb + ((t + 2) % 3) * STAGE_BYTES, tid);
            cp_commit();
        }
        if (t < 16) {
            float best = 3.402823466e+38f; int bi = 0;
            float4 vv;
#pragma unroll
            for (int i = 0; i < 4; i++) {
                vv = (i == 0) ? av0 : (i == 1) ? av1 : (i == 2) ? av2 : av3;
                int c = (lane + i * 32) * 4;
                if (vv.x < best) { best = vv.x; bi = c; }
                if (vv.y < best) { best = vv.y; bi = c + 1; }
                if (vv.z < best) { best = vv.z; bi = c + 2; }
                if (vv.w < best) { best = vv.w; bi = c + 3; }
            }
#pragma unroll
            for (int off = 16; off; off >>= 1) {
                float ov = __shfl_xor_sync(0xffffffffu, best, off);
                int   oi = __shfl_xor_sync(0xffffffffu, bi, off);
                if (ov < best || (ov == best && oi < bi)) { best = ov; bi = oi; }
            }
            if (lane == 0) amin_s[warp * 16 + t] = bi;
            if (t + 1 < 16) {
                const float4* rp = (const float4*)(dbase + (size_t)(t + 1) * NP);
                av0 = rp[lane]; av1 = rp[lane + 32]; av2 = rp[lane + 64]; av3 = rp[lane + 96];
            }
        }
        const float* As = (const float*)(smem + (t % 3) * STAGE_BYTES);
        const uint32_t* Bs32 = (const uint32_t*)(As + A_FLOATS);
        tile_mma(As, Bs32, acc, wm, wn, g, tig);
    }

    // Epilogue
    float b2v = __ldg(b2);
#pragma unroll
    for (int mt = 0; mt < 2; mt++) {
#pragma unroll
        for (int hh = 0; hh < 2; hh++) {
            int rloc = wm * 32 + mt * 16 + hh * 8 + g;
            const float* ph = g_proto_h + (size_t)amin_s[rloc] * H;
            float p = 0.f;
#pragma unroll
            for (int nt = 0; nt < 8; nt++) {
#pragma unroll
                for (int j = 0; j < 2; j++) {
                    int n = wn * 64 + nt * 8 + tig * 2 + j;
                    float v = acc[mt][nt][hh * 2 + j] + ph[n] + b1s[n];
                    p += fmaxf(v, 0.f) * w2s[n];
                }
            }
            p += __shfl_xor_sync(0xffffffffu, p, 1);
            p += __shfl_xor_sync(0xffffffffu, p, 2);
            if (tig == 0) psum[rloc * 2 + wn] = p;
        }
    }
    __syncthreads();
    if (tid < 128) {
        float logit = psum[tid * 2] + psum[tid * 2 + 1] + b2v;
        out[mblock + tid] = 1.f / (1.f + __expf(-logit));
    }
}

// ---------------------------------------------------------------------------
extern "C" void kernel_launch(void* const* d_in, const int* in_sizes, int n_in,
                              void* d_out, int out_size) {
    const float* qf    = (const float*)d_in[0];
    const float* proto = (const float*)d_in[1];
    const float* dist  = (const float*)d_in[2];
    const float* W1    = (const float*)d_in[3];
    const float* b1    = (const float*)d_in[4];
    const float* W2    = (const float*)d_in[5];
    const float* b2    = (const float*)d_in[6];
    float* out = (float*)d_out;

    static int attr_set = 0;
    if (!attr_set) {
        cudaFuncSetAttribute(fused_kernel,
                             cudaFuncAttributeMaxDynamicSharedMemorySize, SMEM_FUSED);
        cudaFuncSetAttribute(proto_mma_kernel,
                             cudaFuncAttributeMaxDynamicSharedMemorySize, SMEM_PROTO);
        attr_set = 1;
    }

    convert_w1t_kernel<<<dim3(2 * D / 32, H / 32), 256>>>(W1);
    proto_mma_kernel<<<dim3(NP / 128, KSPLIT), 256, SMEM_PROTO>>>(proto);
    reduce_ph_kernel<<<NP * H / 4 / 256, 256>>>();
    fused_kernel<<<NQ / 128, 256, SMEM_FUSED>>>(qf, b1, W2, b2, dist, out);
}

// round 6
// speedup vs baseline: 2.1670x; 1.0017x over previous
#include <cuda_runtime.h>
#include <cuda_bf16.h>
#include <cstdint>
#include <math.h>

#define NQ 65536
#define D  1024
#define NP 512
#define H  128
#define KSPLIT 4

// Scratch (device globals; no allocations allowed)
__device__ float    g_ph_part[KSPLIT * NP * H];  // split-k partials of proto @ W1b
__device__ float    g_proto_h[NP * H];           // reduced [512,128]
__device__ uint32_t g_W1T[H * D];                // W1^T as bf16x2: [n][k/2], k pairs

__device__ __forceinline__ uint32_t packbf(float lo, float hi) {
    uint32_t r;
    asm("cvt.rn.bf16x2.f32 %0, %1, %2;" : "=r"(r) : "f"(hi), "f"(lo));
    return r;
}
__device__ __forceinline__ void mma_bf16(float d[4], const uint32_t a[4],
                                         uint32_t b0, uint32_t b1) {
    asm volatile(
        "mma.sync.aligned.m16n8k16.row.col.f32.bf16.bf16.f32 "
        "{%0,%1,%2,%3}, {%4,%5,%6,%7}, {%8,%9}, {%0,%1,%2,%3};\n"
        : "+f"(d[0]), "+f"(d[1]), "+f"(d[2]), "+f"(d[3])
        : "r"(a[0]), "r"(a[1]), "r"(a[2]), "r"(a[3]), "r"(b0), "r"(b1));
}
__device__ __forceinline__ void cpa16(uint32_t s, const void* g) {
    asm volatile("cp.async.cg.shared.global [%0], [%1], 16;\n" :: "r"(s), "l"(g));
}
__device__ __forceinline__ void cp_commit() {
    asm volatile("cp.async.commit_group;\n" ::: "memory");
}

// ---------------------------------------------------------------------------
// Kernel 1: convert+transpose full W1 [2048][128] f32 -> g_W1T [128][2048] bf16
// grid (64, 4) x 256
// ---------------------------------------------------------------------------
__global__ __launch_bounds__(256)
void convert_w1t_kernel(const float* __restrict__ W1) {
    __shared__ float t[32][33];
    int kb = blockIdx.x * 32, nb = blockIdx.y * 32;
    int r = threadIdx.x >> 5, c = threadIdx.x & 31;
#pragma unroll
    for (int i = 0; i < 4; i++)
        t[r + i * 8][c] = W1[(size_t)(kb + r + i * 8) * H + nb + c];
    __syncthreads();
    int rr = threadIdx.x >> 4, c2 = threadIdx.x & 15;
#pragma unroll
    for (int i = 0; i < 2; i++) {
        int n = rr + i * 16;
        g_W1T[(size_t)(nb + n) * (D / 1) /* 2048 bf16 = 1024 u32 */ * 0 +
              (size_t)(nb + n) * 1024 + kb / 2 + c2] =
            packbf(t[c2 * 2][n], t[c2 * 2 + 1][n]);
    }
}

// ---------------------------------------------------------------------------
// Shared GEMM machinery: A fp32 in smem (swizzled 16B chunks), B bf16 [n][k].
// Stage: A 128x32 f32 (16 KB) + B 128 rows x 32 k bf16 (8 KB) = 24 KB. 3 stages.
// ---------------------------------------------------------------------------
#define A_FLOATS     4096                     // 128*32
#define B_U32        2048                     // 128*16
#define STAGE_BYTES  (A_FLOATS * 4 + B_U32 * 4)   // 24576
#define OFF_AUX      (3 * STAGE_BYTES)            // 73728
#define SMEM_FUSED   (OFF_AUX + 128*4 + 128*4 + 128*4 + 256*4)
#define SMEM_PROTO   OFF_AUX

// wcol2048 = u32 column base into g_W1T (k offset / 2)
__device__ __forceinline__ void load_stage(const float* __restrict__ Aglob,
                                           int arow0, int kt, int wk0,
                                           uint32_t stageBase, int tid) {
    uint32_t aB = stageBase;
    uint32_t bB = stageBase + A_FLOATS * 4;
#pragma unroll
    for (int i = 0; i < 4; i++) {               // A: 1024 16B chunks
        int idx = tid + i * 256;
        int r = idx >> 3, c = idx & 7;
        cpa16(aB + (uint32_t)(r * 32 + ((c ^ (r & 7)) * 4)) * 4u,
              Aglob + (size_t)(arow0 + r) * D + kt + c * 4);
    }
#pragma unroll
    for (int i = 0; i < 2; i++) {               // B: 512 16B chunks
        int idx = tid + i * 256;
        int n = idx >> 2, c = idx & 3;
        cpa16(bB + (uint32_t)(n * 16 + ((c ^ ((n >> 1) & 3)) * 4)) * 4u,
              g_W1T + (size_t)n * 1024 + wk0 + (kt >> 1) + c * 4);
    }
}

// One k32 tile of MMAs. As: float*, Bs32: u32*, acc[2][8][4].
__device__ __forceinline__ void tile_mma(const float* As, const uint32_t* Bs32,
                                         float acc[2][8][4],
                                         int wm, int wn, int g, int tig) {
#pragma unroll
    for (int kc = 0; kc < 2; kc++) {
        uint32_t af[2][4];
#pragma unroll
        for (int mt = 0; mt < 2; mt++) {
            int r1 = wm * 32 + mt * 16 + g;
            int r2 = r1 + 8;
            int cl = kc * 4 + (tig >> 1);
            int w  = (tig & 1) * 2;
            int col_lo = ((cl ^ g) << 2) + w;
            int col_hi = (((cl + 2) ^ g) << 2) + w;
            float2 flo1 = *(const float2*)(As + r1 * 32 + col_lo);
            float2 flo2 = *(const float2*)(As + r2 * 32 + col_lo);
            float2 fhi1 = *(const float2*)(As + r1 * 32 + col_hi);
            float2 fhi2 = *(const float2*)(As + r2 * 32 + col_hi);
            af[mt][0] = packbf(flo1.x, flo1.y);
            af[mt][1] = packbf(flo2.x, flo2.y);
            af[mt][2] = packbf(fhi1.x, fhi1.y);
            af[mt][3] = packbf(fhi2.x, fhi2.y);
        }
#pragma unroll
        for (int nt = 0; nt < 8; nt++) {
            int n = wn * 64 + nt * 8 + g;
            const uint32_t* Brow = Bs32 + n * 16;
            int sw = (n >> 1) & 3;
            uint32_t b0 = Brow[(((kc * 2)     ^ sw) << 2) + tig];
            uint32_t b1 = Brow[(((kc * 2 + 1) ^ sw) << 2) + tig];
            mma_bf16(acc[0][nt], af[0], b0, b1);
            mma_bf16(acc[1][nt], af[1], b0, b1);
        }
    }
}

// ---------------------------------------------------------------------------
// Kernel 2: proto partials via bf16 mma. grid (4, KSPLIT) x 256.
// A = prototypes[mb..mb+128], B = W1b cols (u32 offset 512 + ks*128), K=256.
// ---------------------------------------------------------------------------
__global__ __launch_bounds__(256, 2)
void proto_mma_kernel(const float* __restrict__ proto) {
    extern __shared__ char smem[];
    uint32_t sb = (uint32_t)__cvta_generic_to_shared(smem);
    int tid = threadIdx.x;
    int mb = blockIdx.x * 128;
    int ks = blockIdx.y;
    int kt0 = ks * 256;
    int wk0 = 512;                    // W1b starts at k=1024 -> u32 col 512
    int warp = tid >> 5, lane = tid & 31;
    int wm = warp >> 1, wn = warp & 1;
    int g = lane >> 2, tig = lane & 3;

    load_stage(proto, mb, kt0, wk0, sb, tid);               cp_commit();
    load_stage(proto, mb, kt0 + 32, wk0, sb + STAGE_BYTES, tid); cp_commit();

    float acc[2][8][4];
#pragma unroll
    for (int a = 0; a < 2; a++)
#pragma unroll
        for (int b = 0; b < 8; b++)
#pragma unroll
            for (int c = 0; c < 4; c++) acc[a][b][c] = 0.f;

    for (int t = 0; t < 8; t++) {
        if (t + 1 < 8) asm volatile("cp.async.wait_group 1;" ::: "memory");
        else           asm volatile("cp.async.wait_group 0;" ::: "memory");
        __syncthreads();
        if (t + 2 < 8) {
            load_stage(proto, mb, kt0 + (t + 2) * 32, wk0,
                       sb + ((t + 2) % 3) * STAGE_BYTES, tid);
            cp_commit();
        }
        const float* As = (const float*)(smem + (t % 3) * STAGE_BYTES);
        const uint32_t* Bs32 = (const uint32_t*)(As + A_FLOATS);
        tile_mma(As, Bs32, acc, wm, wn, g, tig);
    }

    float* dst = g_ph_part + (size_t)ks * NP * H;
#pragma unroll
    for (int mt = 0; mt < 2; mt++)
#pragma unroll
        for (int hh = 0; hh < 2; hh++)
#pragma unroll
            for (int nt = 0; nt < 8; nt++) {
                int row = mb + wm * 32 + mt * 16 + hh * 8 + g;
                int col = wn * 64 + nt * 8 + tig * 2;
                float2 v = make_float2(acc[mt][nt][hh * 2], acc[mt][nt][hh * 2 + 1]);
                *(float2*)(dst + (size_t)row * H + col) = v;
            }
}

// Kernel 3: reduce partials. grid 64 x 256.
__global__ void reduce_ph_kernel() {
    int i = blockIdx.x * 256 + threadIdx.x;
    float4 s = ((const float4*)g_ph_part)[i];
#pragma unroll
    for (int k = 1; k < KSPLIT; k++) {
        float4 v = ((const float4*)g_ph_part)[k * (NP * H / 4) + i];
        s.x += v.x; s.y += v.y; s.z += v.z; s.w += v.w;
    }
    ((float4*)g_proto_h)[i] = s;
}

// ---------------------------------------------------------------------------
// Kernel 4: fused qf @ W1a (bf16 mma), argmin folded in, MLP epilogue.
// ---------------------------------------------------------------------------
__global__ __launch_bounds__(256, 2)
void fused_kernel(const float* __restrict__ qf, const float* __restrict__ b1,
                  const float* __restrict__ W2, const float* __restrict__ b2,
                  const float* __restrict__ dist, float* __restrict__ out) {
    extern __shared__ char smem[];
    uint32_t sb = (uint32_t)__cvta_generic_to_shared(smem);
    float* b1s    = (float*)(smem + OFF_AUX);
    float* w2s    = b1s + 128;
    int*   amin_s = (int*)(w2s + 128);
    float* psum   = (float*)(amin_s + 128);

    int tid = threadIdx.x;
    int mblock = blockIdx.x * 128;
    int warp = tid >> 5, lane = tid & 31;
    int wm = warp >> 1, wn = warp & 1;
    int g = lane >> 2, tig = lane & 3;

    load_stage(qf, mblock, 0, 0, sb, tid);                cp_commit();
    load_stage(qf, mblock, 32, 0, sb + STAGE_BYTES, tid); cp_commit();

    if (tid < 128) { b1s[tid] = b1[tid]; w2s[tid] = W2[tid]; }

    // argmin: warp handles rows [warp*16, warp*16+16); prefetch row 0
    const float* dbase = dist + (size_t)(mblock + warp * 16) * NP;
    float4 av0, av1, av2, av3;
    {
        const float4* rp = (const float4*)dbase;
        av0 = rp[lane]; av1 = rp[lane + 32]; av2 = rp[lane + 64]; av3 = rp[lane + 96];
    }

    float acc[2][8][4];
#pragma unroll
    for (int a = 0; a < 2; a++)
#pragma unroll
        for (int b = 0; b < 8; b++)
#pragma unroll
            for (int c = 0; c < 4; c++) acc[a][b][c] = 0.f;

    for (int t = 0; t < 32; t++) {
        if (t + 1 < 32) asm volatile("cp.async.wait_group 1;" ::: "memory");
        else            asm volatile("cp.async.wait_group 0;" ::: "memory");
        __syncthreads();
        if (t + 2 < 32) {
            load_stage(qf, mblock, (t + 2) * 32, 0,
                       sb + ((t + 2) % 3) * STAGE_BYTES, tid);
            cp_commit();
        }
        if (t < 16) {
            float best = 3.402823466e+38f; int bi = 0;
            float4 vv;
#pragma unroll
            for (int i = 0; i < 4; i++) {
                vv = (i == 0) ? av0 : (i == 1) ? av1 : (i == 2) ? av2 : av3;
                int c = (lane + i * 32) * 4;
                if (vv.x < best) { best = vv.x; bi = c; }
                if (vv.y < best) { best = vv.y; bi = c + 1; }
                if (vv.z < best) { best = vv.z; bi = c + 2; }
                if (vv.w < best) { best = vv.w; bi = c + 3; }
            }
#pragma unroll
            for (int off = 16; off; off >>= 1) {
                float ov = __shfl_xor_sync(0xffffffffu, best, off);
                int   oi = __shfl_xor_sync(0xffffffffu, bi, off);
                if (ov < best || (ov == best && oi < bi)) { best = ov; bi = oi; }
            }
            if (lane == 0) amin_s[warp * 16 + t] = bi;
            if (t + 1 < 16) {
                const float4* rp = (const float4*)(dbase + (size_t)(t + 1) * NP);
                av0 = rp[lane]; av1 = rp[lane + 32]; av2 = rp[lane + 64]; av3 = rp[lane + 96];
            }
        }
        const float* As = (const float*)(smem + (t % 3) * STAGE_BYTES);
        const uint32_t* Bs32 = (const uint32_t*)(As + A_FLOATS);
        tile_mma(As, Bs32, acc, wm, wn, g, tig);
    }

    // Epilogue
    float b2v = __ldg(b2);
#pragma unroll
    for (int mt = 0; mt < 2; mt++) {
#pragma unroll
        for (int hh = 0; hh < 2; hh++) {
            int rloc = wm * 32 + mt * 16 + hh * 8 + g;
            const float* ph = g_proto_h + (size_t)amin_s[rloc] * H;
            float p = 0.f;
#pragma unroll
            for (int nt = 0; nt < 8; nt++) {
#pragma unroll
                for (int j = 0; j < 2; j++) {
                    int n = wn * 64 + nt * 8 + tig * 2 + j;
                    float v = acc[mt][nt][hh * 2 + j] + ph[n] + b1s[n];
                    p += fmaxf(v, 0.f) * w2s[n];
                }
            }
            p += __shfl_xor_sync(0xffffffffu, p, 1);
            p += __shfl_xor_sync(0xffffffffu, p, 2);
            if (tig == 0) psum[rloc * 2 + wn] = p;
        }
    }
    __syncthreads();
    if (tid < 128) {
        float logit = psum[tid * 2] + psum[tid * 2 + 1] + b2v;
        out[mblock + tid] = 1.f / (1.f + __expf(-logit));
    }
}

// ---------------------------------------------------------------------------
extern "C" void kernel_launch(void* const* d_in, const int* in_sizes, int n_in,
                              void* d_out, int out_size) {
    const float* qf    = (const float*)d_in[0];
    const float* proto = (const float*)d_in[1];
    const float* dist  = (const float*)d_in[2];
    const float* W1    = (const float*)d_in[3];
    const float* b1    = (const float*)d_in[4];
    const float* W2    = (const float*)d_in[5];
    const float* b2    = (const float*)d_in[6];
    float* out = (float*)d_out;

    static int attr_set = 0;
    if (!attr_set) {
        cudaFuncSetAttribute(fused_kernel,
                             cudaFuncAttributeMaxDynamicSharedMemorySize, SMEM_FUSED);
        cudaFuncSetAttribute(proto_mma_kernel,
                             cudaFuncAttributeMaxDynamicSharedMemorySize, SMEM_PROTO);
        attr_set = 1;
    }

    convert_w1t_kernel<<<dim3(2 * D / 32, H / 32), 256>>>(W1);
    proto_mma_kernel<<<dim3(NP / 128, KSPLIT), 256, SMEM_PROTO>>>(proto);
    reduce_ph_kernel<<<NP * H / 4 / 256, 256>>>();
    fused_kernel<<<NQ / 128, 256, SMEM_FUSED>>>(qf, b1, W2, b2, dist, out);
}

// round 8
// speedup vs baseline: 2.2830x; 1.0535x over previous
#include <cuda_runtime.h>
#include <cuda_bf16.h>
#include <cstdint>
#include <math.h>

#define NQ 65536
#define D  1024
#define NP 512
#define H  128
#define KSPLIT 4

// Scratch (device globals; no allocations allowed)
__device__ float    g_ph_part[KSPLIT * NP * H];  // split-k partials of proto @ W1b
__device__ float    g_proto_h[NP * H];           // reduced [512,128]
__device__ uint32_t g_W1T[H * D];                // W1^T as bf16x2: [n][k/2]

__device__ __forceinline__ uint32_t packbf(float lo, float hi) {
    uint32_t r;
    asm("cvt.rn.bf16x2.f32 %0, %1, %2;" : "=r"(r) : "f"(hi), "f"(lo));
    return r;
}
__device__ __forceinline__ void mma_bf16(float d[4], const uint32_t a[4],
                                         uint32_t b0, uint32_t b1) {
    asm volatile(
        "mma.sync.aligned.m16n8k16.row.col.f32.bf16.bf16.f32 "
        "{%0,%1,%2,%3}, {%4,%5,%6,%7}, {%8,%9}, {%0,%1,%2,%3};\n"
        : "+f"(d[0]), "+f"(d[1]), "+f"(d[2]), "+f"(d[3])
        : "r"(a[0]), "r"(a[1]), "r"(a[2]), "r"(a[3]), "r"(b0), "r"(b1));
}
__device__ __forceinline__ void cpa16(uint32_t s, const void* g) {
    asm volatile("cp.async.cg.shared.global [%0], [%1], 16;\n" :: "r"(s), "l"(g));
}
__device__ __forceinline__ void cp_commit() {
    asm volatile("cp.async.commit_group;\n" ::: "memory");
}
__device__ __forceinline__ void ldsm4(uint32_t r[4], uint32_t a) {
    asm volatile("ldmatrix.sync.aligned.m8n8.x4.shared.b16 {%0,%1,%2,%3}, [%4];"
                 : "=r"(r[0]), "=r"(r[1]), "=r"(r[2]), "=r"(r[3]) : "r"(a));
}

// ---------------------------------------------------------------------------
// Kernel 1: convert+transpose full W1 [2048][128] f32 -> g_W1T [128][2048] bf16
// ---------------------------------------------------------------------------
__global__ __launch_bounds__(256)
void convert_w1t_kernel(const float* __restrict__ W1) {
    __shared__ float t[32][33];
    int kb = blockIdx.x * 32, nb = blockIdx.y * 32;
    int r = threadIdx.x >> 5, c = threadIdx.x & 31;
#pragma unroll
    for (int i = 0; i < 4; i++)
        t[r + i * 8][c] = W1[(size_t)(kb + r + i * 8) * H + nb + c];
    __syncthreads();
    int rr = threadIdx.x >> 4, c2 = threadIdx.x & 15;
#pragma unroll
    for (int i = 0; i < 2; i++) {
        int n = rr + i * 16;
        g_W1T[(size_t)(nb + n) * 1024 + kb / 2 + c2] =
            packbf(t[c2 * 2][n], t[c2 * 2 + 1][n]);
    }
}

// ---------------------------------------------------------------------------
// Shared machinery. Tiles: A bf16 [128 m][32 k] (8 KB, 64B rows, swizzled),
// B bf16 [128 n][32 k] (8 KB, same layout). A: LDG->cvt->STS double buffer.
// B: cp.async 3-stage ring.
// smem: bufA[2] @ 0, bufB[3] @ 16384, aux @ 40960.
// ---------------------------------------------------------------------------
#define ABUF   0
#define BBUF   16384
#define OFF_AUX 40960
#define SMEM_FUSED (OFF_AUX + 512 + 512 + 512 + 1024)
#define SMEM_PROTO OFF_AUX

__device__ __forceinline__ void load_A_regs(float4 (&fa)[4],
                                            const float* __restrict__ A,
                                            int row0, int kt, int tid) {
#pragma unroll
    for (int i = 0; i < 2; i++) {
        int p = tid + i * 256;
        int r = p >> 2, c = p & 3;
        const float4* src = (const float4*)(A + (size_t)(row0 + r) * D + kt + c * 8);
        fa[2 * i]     = src[0];
        fa[2 * i + 1] = src[1];
    }
}
__device__ __forceinline__ void sts_A(const float4 (&fa)[4], uint32_t aB, int tid) {
#pragma unroll
    for (int i = 0; i < 2; i++) {
        int p = tid + i * 256;
        int r = p >> 2, c = p & 3;
        uint32_t u0 = packbf(fa[2 * i].x, fa[2 * i].y);
        uint32_t u1 = packbf(fa[2 * i].z, fa[2 * i].w);
        uint32_t u2 = packbf(fa[2 * i + 1].x, fa[2 * i + 1].y);
        uint32_t u3 = packbf(fa[2 * i + 1].z, fa[2 * i + 1].w);
        uint32_t ad = aB + (uint32_t)((r >> 1) * 128 + (r & 1) * 64 +
                                      ((c ^ ((r >> 1) & 3)) << 4));
        asm volatile("st.shared.v4.b32 [%0], {%1,%2,%3,%4};"
                     :: "r"(ad), "r"(u0), "r"(u1), "r"(u2), "r"(u3));
    }
}
// kt_u32 = u32 column offset into g_W1T rows (wk0 + kt/2)
__device__ __forceinline__ void load_B_stage(int kt_u32, uint32_t bB, int tid) {
#pragma unroll
    for (int i = 0; i < 2; i++) {
        int p = tid + i * 256;
        int n = p >> 2, c = p & 3;
        cpa16(bB + (uint32_t)((n >> 1) * 128 + (n & 1) * 64 +
                              ((c ^ ((n >> 1) & 3)) << 4)),
              g_W1T + (size_t)n * 1024 + kt_u32 + c * 4);
    }
}

__device__ __forceinline__ void tile_mma(uint32_t aB, uint32_t bB,
                                         float acc[2][8][4],
                                         int wm, int wn, int lane) {
    int grp = lane >> 3, l7 = lane & 7;
#pragma unroll
    for (int kc = 0; kc < 2; kc++) {
        uint32_t af[2][4];
#pragma unroll
        for (int mt = 0; mt < 2; mt++) {
            int mrow = wm * 32 + mt * 16 + (grp & 1) * 8 + l7;
            int c16 = kc * 2 + (grp >> 1);
            uint32_t ad = aB + (uint32_t)((mrow >> 1) * 128 + (mrow & 1) * 64 +
                                          ((c16 ^ ((mrow >> 1) & 3)) << 4));
            ldsm4(af[mt], ad);
        }
#pragma unroll
        for (int ntp = 0; ntp < 4; ntp++) {
            int n = wn * 64 + ntp * 16 + (grp >> 1) * 8 + l7;
            int c16 = kc * 2 + (grp & 1);
            uint32_t bd = bB + (uint32_t)((n >> 1) * 128 + (n & 1) * 64 +
                                          ((c16 ^ ((n >> 1) & 3)) << 4));
            uint32_t b[4];
            ldsm4(b, bd);
            mma_bf16(acc[0][ntp * 2],     af[0], b[0], b[1]);
            mma_bf16(acc[1][ntp * 2],     af[1], b[0], b[1]);
            mma_bf16(acc[0][ntp * 2 + 1], af[0], b[2], b[3]);
            mma_bf16(acc[1][ntp * 2 + 1], af[1], b[2], b[3]);
        }
    }
}

// ---------------------------------------------------------------------------
// Kernel 2: proto partials via bf16 mma. grid (4, KSPLIT) x 256. K = 256.
// ---------------------------------------------------------------------------
__global__ __launch_bounds__(256, 2)
void proto_mma_kernel(const float* __restrict__ proto) {
    extern __shared__ char smem[];
    uint32_t sb = (uint32_t)__cvta_generic_to_shared(smem);
    int tid = threadIdx.x;
    int mb = blockIdx.x * 128;
    int ks = blockIdx.y;
    int kt0 = ks * 256;
    int wu0 = 512 + ks * 128;            // u32 col base into g_W1T (W1b half)
    int warp = tid >> 5, lane = tid & 31;
    int wm = warp >> 1, wn = warp & 1;
    int g = lane >> 2, tig = lane & 3;

    float4 fa[4];
    load_A_regs(fa, proto, mb, kt0, tid);
    load_B_stage(wu0,      sb + BBUF,        tid); cp_commit();
    load_B_stage(wu0 + 16, sb + BBUF + 8192, tid); cp_commit();
    sts_A(fa, sb + ABUF, tid);
    load_A_regs(fa, proto, mb, kt0 + 32, tid);

    float acc[2][8][4];
#pragma unroll
    for (int a = 0; a < 2; a++)
#pragma unroll
        for (int b = 0; b < 8; b++)
#pragma unroll
            for (int c = 0; c < 4; c++) acc[a][b][c] = 0.f;

    for (int t = 0; t < 8; t++) {
        if (t < 7) asm volatile("cp.async.wait_group 1;" ::: "memory");
        else       asm volatile("cp.async.wait_group 0;" ::: "memory");
        __syncthreads();
        if (t < 7) sts_A(fa, sb + ABUF + ((t + 1) & 1) * 8192, tid);
        if (t < 6) {
            load_A_regs(fa, proto, mb, kt0 + (t + 2) * 32, tid);
            load_B_stage(wu0 + (t + 2) * 16, sb + BBUF + ((t + 2) % 3) * 8192, tid);
            cp_commit();
        }
        tile_mma(sb + ABUF + (t & 1) * 8192, sb + BBUF + (t % 3) * 8192,
                 acc, wm, wn, lane);
    }

    float* dst = g_ph_part + (size_t)ks * NP * H;
#pragma unroll
    for (int mt = 0; mt < 2; mt++)
#pragma unroll
        for (int hh = 0; hh < 2; hh++)
#pragma unroll
            for (int nt = 0; nt < 8; nt++) {
                int row = mb + wm * 32 + mt * 16 + hh * 8 + g;
                int col = wn * 64 + nt * 8 + tig * 2;
                float2 v = make_float2(acc[mt][nt][hh * 2], acc[mt][nt][hh * 2 + 1]);
                *(float2*)(dst + (size_t)row * H + col) = v;
            }
}

// Kernel 3: reduce partials. grid 64 x 256.
__global__ void reduce_ph_kernel() {
    int i = blockIdx.x * 256 + threadIdx.x;
    float4 s = ((const float4*)g_ph_part)[i];
#pragma unroll
    for (int k = 1; k < KSPLIT; k++) {
        float4 v = ((const float4*)g_ph_part)[k * (NP * H / 4) + i];
        s.x += v.x; s.y += v.y; s.z += v.z; s.w += v.w;
    }
    ((float4*)g_proto_h)[i] = s;
}

// ---------------------------------------------------------------------------
// Kernel 4: fused qf @ W1a (bf16 mma + ldmatrix), argmin folded (half-row per
// iteration, all 32 iters), MLP epilogue.
// ---------------------------------------------------------------------------
__global__ __launch_bounds__(256, 2)
void fused_kernel(const float* __restrict__ qf, const float* __restrict__ b1,
                  const float* __restrict__ W2, const float* __restrict__ b2,
                  const float* __restrict__ dist, float* __restrict__ out) {
    extern __shared__ char smem[];
    uint32_t sb = (uint32_t)__cvta_generic_to_shared(smem);
    float* b1s    = (float*)(smem + OFF_AUX);
    float* w2s    = b1s + 128;
    int*   amin_s = (int*)(w2s + 128);
    float* psum   = (float*)(amin_s + 128);

    int tid = threadIdx.x;
    int mblock = blockIdx.x * 128;
    int warp = tid >> 5, lane = tid & 31;
    int wm = warp >> 1, wn = warp & 1;
    int g = lane >> 2, tig = lane & 3;

    float4 fa[4];
    load_A_regs(fa, qf, mblock, 0, tid);
    load_B_stage(0,  sb + BBUF,        tid); cp_commit();
    load_B_stage(16, sb + BBUF + 8192, tid); cp_commit();
    sts_A(fa, sb + ABUF, tid);
    load_A_regs(fa, qf, mblock, 32, tid);

    if (tid < 128) { b1s[tid] = b1[tid]; w2s[tid] = W2[tid]; }

    // argmin: warp owns rows [warp*16, warp*16+16); one half-row per iter.
    const float* dbase = dist + (size_t)(mblock + warp * 16) * NP;
    float4 av0, av1;
    {   // prefetch half-row 0 (row 0, part 0)
        const float4* rp = (const float4*)dbase;
        av0 = rp[lane]; av1 = rp[lane + 32];
    }
    float bestc = 0.f; int bic = 0;

    float acc[2][8][4];
#pragma unroll
    for (int a = 0; a < 2; a++)
#pragma unroll
        for (int b = 0; b < 8; b++)
#pragma unroll
            for (int c = 0; c < 4; c++) acc[a][b][c] = 0.f;

    for (int t = 0; t < 32; t++) {
        if (t < 31) asm volatile("cp.async.wait_group 1;" ::: "memory");
        else        asm volatile("cp.async.wait_group 0;" ::: "memory");
        __syncthreads();
        if (t < 31) sts_A(fa, sb + ABUF + ((t + 1) & 1) * 8192, tid);
        if (t < 30) {
            load_A_regs(fa, qf, mblock, (t + 2) * 32, tid);
            load_B_stage((t + 2) * 16, sb + BBUF + ((t + 2) % 3) * 8192, tid);
            cp_commit();
        }
        {   // argmin half-row t
            int row = t >> 1, part = t & 1;
            int cb = part * 256 + lane * 4;
            float best = av0.x; int bi = cb;
            if (av0.y < best) { best = av0.y; bi = cb + 1; }
            if (av0.z < best) { best = av0.z; bi = cb + 2; }
            if (av0.w < best) { best = av0.w; bi = cb + 3; }
            if (av1.x < best) { best = av1.x; bi = cb + 128; }
            if (av1.y < best) { best = av1.y; bi = cb + 129; }
            if (av1.z < best) { best = av1.z; bi = cb + 130; }
            if (av1.w < best) { best = av1.w; bi = cb + 131; }
            if (part == 0) { bestc = best; bic = bi; }
            else {
                if (bestc < best || (bestc == best && bic < bi)) { best = bestc; bi = bic; }
#pragma unroll
                for (int off = 16; off; off >>= 1) {
                    float ov = __shfl_xor_sync(0xffffffffu, best, off);
                    int   oi = __shfl_xor_sync(0xffffffffu, bi, off);
                    if (ov < best || (ov == best && oi < bi)) { best = ov; bi = oi; }
                }
                if (lane == 0) amin_s[warp * 16 + row] = bi;
            }
            if (t + 1 < 32) {   // prefetch next half-row
                int nr = (t + 1) >> 1, np = (t + 1) & 1;
                const float4* rp = (const float4*)(dbase + (size_t)nr * NP + np * 256);
                av0 = rp[lane]; av1 = rp[lane + 32];
            }
        }
        tile_mma(sb + ABUF + (t & 1) * 8192, sb + BBUF + (t % 3) * 8192,
                 acc, wm, wn, lane);
    }
    __syncthreads();   // amin_s written up to t=31; make visible cross-warp

    // Epilogue
    float b2v = __ldg(b2);
#pragma unroll
    for (int mt = 0; mt < 2; mt++) {
#pragma unroll
        for (int hh = 0; hh < 2; hh++) {
            int rloc = wm * 32 + mt * 16 + hh * 8 + g;
            const float* ph = g_proto_h + (size_t)amin_s[rloc] * H;
            float p = 0.f;
#pragma unroll
            for (int nt = 0; nt < 8; nt++) {
#pragma unroll
                for (int j = 0; j < 2; j++) {
                    int n = wn * 64 + nt * 8 + tig * 2 + j;
                    float v = acc[mt][nt][hh * 2 + j] + ph[n] + b1s[n];
                    p += fmaxf(v, 0.f) * w2s[n];
                }
            }
            p += __shfl_xor_sync(0xffffffffu, p, 1);
            p += __shfl_xor_sync(0xffffffffu, p, 2);
            if (tig == 0) psum[rloc * 2 + wn] = p;
        }
    }
    __syncthreads();
    if (tid < 128) {
        float logit = psum[tid * 2] + psum[tid * 2 + 1] + b2v;
        out[mblock + tid] = 1.f / (1.f + __expf(-logit));
    }
}

// ---------------------------------------------------------------------------
extern "C" void kernel_launch(void* const* d_in, const int* in_sizes, int n_in,
                              void* d_out, int out_size) {
    const float* qf    = (const float*)d_in[0];
    const float* proto = (const float*)d_in[1];
    const float* dist  = (const float*)d_in[2];
    const float* W1    = (const float*)d_in[3];
    const float* b1    = (const float*)d_in[4];
    const float* W2    = (const float*)d_in[5];
    const float* b2    = (const float*)d_in[6];
    float* out = (float*)d_out;

    static int attr_set = 0;
    if (!attr_set) {
        cudaFuncSetAttribute(fused_kernel,
                             cudaFuncAttributeMaxDynamicSharedMemorySize, SMEM_FUSED);
        cudaFuncSetAttribute(proto_mma_kernel,
                             cudaFuncAttributeMaxDynamicSharedMemorySize, SMEM_PROTO);
        attr_set = 1;
    }

    convert_w1t_kernel<<<dim3(2 * D / 32, H / 32), 256>>>(W1);
    proto_mma_kernel<<<dim3(NP / 128, KSPLIT), 256, SMEM_PROTO>>>(proto);
    reduce_ph_kernel<<<NP * H / 4 / 256, 256>>>();
    fused_kernel<<<NQ / 128, 256, SMEM_FUSED>>>(qf, b1, W2, b2, dist, out);
}